// round 17
// baseline (speedup 1.0000x reference)
#include <cuda_runtime.h>
#include <cuda_bf16.h>
#include <cstdint>

#define BB 16
#define CC 512
#define NN 4096
#define EPSF 1e-6f

// ---------------- device scratch (allocation-free rule) ----------------
__device__ float g_srn   [BB * NN];
__device__ float g_colsum[BB * NN];
__device__ float g_tacc  [BB * CC];                 // tailor accumulators
__device__ uint8_t g_y8 [(size_t)BB * CC * NN];     // e4m3(x*srn) [b,c,n]
__device__ uint8_t g_y8T[(size_t)BB * NN * CC];     // e4m3(x*srn) [b,n,c]
__device__ uint8_t g_Mb8[(size_t)BB * CC * CC];     // e4m3(M)     [b,c,m]
__device__ __nv_bfloat16 g_Mp[(size_t)4 * BB * 10 * 16384];  // split-K partials (bf16)

// ---------------- helpers ----------------
__device__ __forceinline__ uint32_t smem_u32(const void* p) {
    uint32_t a;
    asm("{ .reg .u64 t; cvta.to.shared.u64 t, %1; cvt.u32.u64 %0, t; }" : "=r"(a) : "l"(p));
    return a;
}
__device__ __forceinline__ uint16_t pack_e4m3x2(float lo, float hi) {
    uint16_t r;
    asm("cvt.rn.satfinite.e4m3x2.f32 %0, %1, %2;" : "=h"(r) : "f"(hi), "f"(lo));
    return r;
}
__device__ __forceinline__ uint32_t pack_e4m3x4(float f0, float f1, float f2, float f3) {
    uint16_t lo = pack_e4m3x2(f0, f1);
    uint16_t hi = pack_e4m3x2(f2, f3);
    return (uint32_t)lo | ((uint32_t)hi << 16);
}
__device__ __forceinline__ uint32_t pack_bf16x2(float lo, float hi) {
    uint32_t r;
    asm("cvt.rn.bf16x2.f32 %0, %1, %2;" : "=r"(r) : "f"(hi), "f"(lo));
    return r;
}
__device__ __forceinline__ void ldsm_x4(uint32_t& r0, uint32_t& r1, uint32_t& r2,
                                        uint32_t& r3, uint32_t addr) {
    asm volatile("ldmatrix.sync.aligned.m8n8.x4.shared.b16 {%0,%1,%2,%3}, [%4];"
                 : "=r"(r0), "=r"(r1), "=r"(r2), "=r"(r3) : "r"(addr));
}
__device__ __forceinline__ void mma_fp8(float* c, const uint32_t* a,
                                        uint32_t b0, uint32_t b1) {
    asm volatile(
        "mma.sync.aligned.m16n8k32.row.col.f32.e4m3.e4m3.f32 "
        "{%0,%1,%2,%3}, {%4,%5,%6,%7}, {%8,%9}, {%0,%1,%2,%3};"
        : "+f"(c[0]), "+f"(c[1]), "+f"(c[2]), "+f"(c[3])
        : "r"(a[0]), "r"(a[1]), "r"(a[2]), "r"(a[3]), "r"(b0), "r"(b1));
}
__device__ __forceinline__ void cp16(uint32_t dst, const void* src) {
    asm volatile("cp.async.cg.shared.global [%0], [%1], 16;" :: "r"(dst), "l"(src));
}
#define CP_COMMIT() asm volatile("cp.async.commit_group;" ::: "memory")
#define CP_WAIT1()  asm volatile("cp.async.wait_group 1;"  ::: "memory")

// GEMM tiles 128x128, BK = 128 fp8 (128 B); smem row = 144 B
#define STG_A    18432u
#define STG_SZ   36864u
#define NSTAGE   3
#define SM_DYN   (NSTAGE * STG_SZ)

// prep smem: S[512][65] floats + aux
#define PREP_STRIDE 65
#define PREP_AUX    (512 * PREP_STRIDE)
#define PREP_SMEM   ((512 * PREP_STRIDE + 512 + 512 + 64 + 64) * 4)

// ===========================================================================
// Kernel 1: fused stats + convert. One CTA = full channel column x 64 n.
// ===========================================================================
__global__ void __launch_bounds__(512) prep_kernel(const float* __restrict__ x) {
    extern __shared__ float PS[];
    float* S    = PS;                       // [512][65]
    float* ssp  = PS + PREP_AUX;            // [8][64]
    float* csp  = ssp + 512;                // [8][64]
    float* srnS = csp + 512;                // [64]
    float* wS   = srnS + 64;                // [64]

    const int b = blockIdx.y, n0 = blockIdx.x * 64;
    const int t = threadIdx.x;
    const float* xb = x + (size_t)b * CC * NN + n0;

#pragma unroll
    for (int i = 0; i < 16; i++) {
        int idx = t + i * 512;
        int c = idx >> 4, q = idx & 15;
        float4 v = *(const float4*)(xb + (size_t)c * NN + q * 4);
        float* s = &S[c * PREP_STRIDE + q * 4];
        s[0] = v.x; s[1] = v.y; s[2] = v.z; s[3] = v.w;
    }
    __syncthreads();

    {
        int n = t & 63, ch = t >> 6;
        float ss = 0.f, cs = 0.f;
#pragma unroll 8
        for (int i = 0; i < 64; i++) {
            float v = S[(ch * 64 + i) * PREP_STRIDE + n];
            ss = fmaf(v, v, ss);
            cs += v;
        }
        ssp[ch * 64 + n] = ss;
        csp[ch * 64 + n] = cs;
    }
    __syncthreads();
    if (t < 64) {
        float ss = 0.f, cs = 0.f;
#pragma unroll
        for (int ch = 0; ch < 8; ch++) { ss += ssp[ch * 64 + t]; cs += csp[ch * 64 + t]; }
        float rn = rsqrtf(ss);
        float sr = sqrtf(rn);
        srnS[t] = sr;
        wS[t]   = rn * fmaf(cs, rn, EPSF);
        g_srn   [b * NN + n0 + t] = sr;
        g_colsum[b * NN + n0 + t] = cs;
    }
    __syncthreads();

    {
        float d = 0.f;
        const float* row = &S[t * PREP_STRIDE];
#pragma unroll 8
        for (int n = 0; n < 64; n++) d = fmaf(row[n], wS[n], d);
        atomicAdd(&g_tacc[b * CC + t], d);
    }

#pragma unroll
    for (int i = 0; i < 16; i++) {
        int idx = t + i * 512;
        int c = idx >> 4, q = idx & 15;
        const float* s = &S[c * PREP_STRIDE + q * 4];
        const float* sr = &srnS[q * 4];
        *(uint32_t*)(g_y8 + (size_t)(b * CC + c) * NN + n0 + q * 4) =
            pack_e4m3x4(s[0] * sr[0], s[1] * sr[1], s[2] * sr[2], s[3] * sr[3]);
    }

#pragma unroll
    for (int i = 0; i < 16; i++) {
        int idx = t + i * 512;
        int n = idx >> 7, c4 = (idx & 127) * 4;
        float sr = srnS[n];
        float y0 = S[(c4 + 0) * PREP_STRIDE + n] * sr;
        float y1 = S[(c4 + 1) * PREP_STRIDE + n] * sr;
        float y2 = S[(c4 + 2) * PREP_STRIDE + n] * sr;
        float y3 = S[(c4 + 3) * PREP_STRIDE + n] * sr;
        *(uint32_t*)(g_y8T + ((size_t)b * NN + n0 + n) * CC + c4) =
            pack_e4m3x4(y0, y1, y2, y3);
    }
}

// ===========================================================================
// Fragment loaders (fp8 K-major; k-step = 32 B)
// ===========================================================================
__device__ __forceinline__ void lda_frag(uint32_t a[2][4], uint32_t sa,
                                         int wm, int lane, int ks) {
    const uint32_t lrow = lane & 15, lch = (lane >> 4) << 4;
#pragma unroll
    for (int mt = 0; mt < 2; mt++)
        ldsm_x4(a[mt][0], a[mt][1], a[mt][2], a[mt][3],
                sa + (wm * 32 + mt * 16 + lrow) * 144 + ks * 32 + lch);
}
__device__ __forceinline__ void ldb_nt(uint32_t bf[4], uint32_t sb,
                                       int wn, int lane, int ks, int p) {
    const uint32_t lrow = lane & 15, lch = (lane >> 4) << 4;
    ldsm_x4(bf[0], bf[1], bf[2], bf[3],
            sb + (wn * 64 + p * 16 + lrow) * 144 + ks * 32 + lch);
}
__device__ __forceinline__ void mma_group(float acc[2][8][4], uint32_t a[2][4],
                                          uint32_t bf[4], int p) {
#pragma unroll
    for (int mt = 0; mt < 2; mt++) {
        mma_fp8(acc[mt][2 * p],     a[mt], bf[0], bf[2]);
        mma_fp8(acc[mt][2 * p + 1], a[mt], bf[1], bf[3]);
    }
}
__device__ __forceinline__ void compute_stage(uint32_t sa, uint32_t sbB,
                                              int wm, int wn, int lane,
                                              float acc[2][8][4]) {
    uint32_t a[2][2][4], bf[2][4];
    lda_frag(a[0], sa, wm, lane, 0);
    ldb_nt(bf[0], sbB, wn, lane, 0, 0);
#pragma unroll
    for (int ks = 0; ks < 4; ks++) {
#pragma unroll
        for (int p = 0; p < 4; p++) {
            int cur = (ks * 4 + p) & 1, nxt = cur ^ 1;
            if (p < 3) ldb_nt(bf[nxt], sbB, wn, lane, ks, p + 1);
            else if (ks < 3) {
                ldb_nt(bf[nxt], sbB, wn, lane, ks + 1, 0);
                lda_frag(a[(ks + 1) & 1], sa, wm, lane, ks + 1);
            }
            mma_group(acc, a[ks & 1], bf[cur], p);
        }
    }
}

// ===========================================================================
// Kernel 2: GEMM1 (symmetric, split-K=4)  M = y.y^T upper-tri tiles, fp8
// ===========================================================================
__global__ void __launch_bounds__(256, 2) gemm1_mma() {
    extern __shared__ __align__(128) char dsm[];
    const uint32_t sb0 = smem_u32(dsm);
    const int tid = threadIdx.x, lane = tid & 31, warp = tid >> 5;
    const int wm = warp & 3, wn = warp >> 2;
    const int TI[10] = {0,0,0,0,1,1,1,2,2,3};
    const int TJ[10] = {0,1,2,3,1,2,3,2,3,3};
    const int tile = blockIdx.x, sp = blockIdx.y, b = blockIdx.z;
    const int cb = TI[tile] * 128, mb = TJ[tile] * 128;
    const int kbase = sp * 1024;
    const uint8_t* A  = g_y8 + (size_t)(b * CC + cb) * NN;
    const uint8_t* Bp = g_y8 + (size_t)(b * CC + mb) * NN;

    float acc[2][8][4];
#pragma unroll
    for (int i = 0; i < 2; i++)
#pragma unroll
        for (int j = 0; j < 8; j++)
#pragma unroll
            for (int q = 0; q < 4; q++) acc[i][j][q] = 0.f;

    auto issue = [&](uint32_t sbase, int k0) {
#pragma unroll
        for (int i = 0; i < 8; i++) {
            int f = tid + i * 256;
            int half = f >> 10;
            int r = (f >> 3) & 127, ch = f & 7;
            const uint8_t* src =
                (half ? Bp + (size_t)r * NN : A + (size_t)r * NN) + k0 + ch * 16;
            cp16(sbase + half * STG_A + r * 144 + ch * 16, src);
        }
    };

    issue(sb0,          kbase);       CP_COMMIT();
    issue(sb0 + STG_SZ, kbase + 128); CP_COMMIT();

    const int KT = 8;
    for (int kt = 0; kt < KT; kt++) {
        CP_WAIT1();
        __syncthreads();
        int nk = kt + 2;
        if (nk < KT) issue(sb0 + (nk % NSTAGE) * STG_SZ, kbase + nk * 128);
        CP_COMMIT();
        uint32_t s = sb0 + (kt % NSTAGE) * STG_SZ;
        compute_stage(s, s + STG_A, wm, wn, lane, acc);
    }

    __nv_bfloat16* Mp = g_Mp + (((size_t)sp * BB + b) * 10 + tile) * 16384;
#pragma unroll
    for (int mt = 0; mt < 2; mt++) {
        int r0 = wm * 32 + mt * 16 + (lane >> 2);
#pragma unroll
        for (int nt = 0; nt < 8; nt++) {
            int col = wn * 64 + nt * 8 + 2 * (lane & 3);
            *(uint32_t*)(Mp + r0 * 128 + col) =
                pack_bf16x2(acc[mt][nt][0], acc[mt][nt][1]);
            *(uint32_t*)(Mp + (r0 + 8) * 128 + col) =
                pack_bf16x2(acc[mt][nt][2], acc[mt][nt][3]);
        }
    }
}

// ===========================================================================
// Kernel 3: reduce bf16 split-K partials -> fp8 Mb (+ mirrored tile)
// ===========================================================================
__global__ void __launch_bounds__(256) reduce_mirror() {
    __shared__ float S[64][65];
    const int TI[10] = {0,0,0,0,1,1,1,2,2,3};
    const int TJ[10] = {0,1,2,3,1,2,3,2,3,3};
    const int q = blockIdx.x, t = blockIdx.y, b = blockIdx.z;
    const int ii = TI[t], jj = TJ[t];
    const int qr = q >> 1, qc = q & 1;
    const int tid = threadIdx.x;
    const size_t spstride = (size_t)BB * 10 * 16384;
    const __nv_bfloat16* base = g_Mp + ((size_t)b * 10 + t) * 16384;
    uint8_t* Mo = g_Mb8 + (size_t)b * CC * CC;
    const int cb = ii * 128, mb = jj * 128;

#pragma unroll
    for (int e = 0; e < 8; e++) {
        int idx = tid + e * 256;
        int r = idx >> 5, p = idx & 31;
        int off = (qr * 64 + r) * 128 + qc * 64 + 2 * p;
        float2 s0 = __bfloat1622float2(*(const __nv_bfloat162*)(base + off));
        float2 s1 = __bfloat1622float2(*(const __nv_bfloat162*)(base + spstride + off));
        float2 s2 = __bfloat1622float2(*(const __nv_bfloat162*)(base + 2 * spstride + off));
        float2 s3 = __bfloat1622float2(*(const __nv_bfloat162*)(base + 3 * spstride + off));
        float sx = s0.x + s1.x + s2.x + s3.x;
        float sy = s0.y + s1.y + s2.y + s3.y;
        *(uint16_t*)(Mo + (size_t)(cb + qr * 64 + r) * CC + mb + qc * 64 + 2 * p) =
            pack_e4m3x2(sx, sy);
        S[r][2 * p] = sx; S[r][2 * p + 1] = sy;
    }
    if (ii == jj) return;
    __syncthreads();
#pragma unroll
    for (int e = 0; e < 8; e++) {
        int idx = tid + e * 256;
        int m = idx >> 5, p = idx & 31;
        uint16_t v = pack_e4m3x2(S[2 * p][m], S[2 * p + 1][m]);
        *(uint16_t*)(Mo + (size_t)(mb + qc * 64 + m) * CC + cb + qr * 64 + 2 * p) = v;
    }
}

// ===========================================================================
// Kernel 4: GEMM2  S'[c,n] = sum_m Mb[c,m]*y8T[n,m]; coalesced fused epilogue:
//   tailor = 1/(N + tacc[c]);  out = x + gamma*tailor*(colsum + srn*S')
// ===========================================================================
__global__ void __launch_bounds__(256, 2) gemm2_mma(const float* __restrict__ x,
                                                    const float* __restrict__ gptr,
                                                    float* __restrict__ out) {
    extern __shared__ __align__(128) char dsm[];
    const uint32_t sb0 = smem_u32(dsm);
    const int tid = threadIdx.x, lane = tid & 31, warp = tid >> 5;
    const int wm = warp & 3, wn = warp >> 2;
    const int b = blockIdx.z, cb = blockIdx.y * 128, nb = blockIdx.x * 128;
    const uint8_t* A  = g_Mb8 + (size_t)(b * CC + cb) * CC;
    const uint8_t* Bp = g_y8T + ((size_t)b * NN + nb) * CC;

    float acc[2][8][4];
#pragma unroll
    for (int i = 0; i < 2; i++)
#pragma unroll
        for (int j = 0; j < 8; j++)
#pragma unroll
            for (int q = 0; q < 4; q++) acc[i][j][q] = 0.f;

    auto issue = [&](uint32_t sbase, int k0) {
#pragma unroll
        for (int i = 0; i < 8; i++) {
            int f = tid + i * 256;
            int half = f >> 10;
            int r = (f >> 3) & 127, ch = f & 7;
            const uint8_t* src =
                (half ? Bp + (size_t)r * CC : A + (size_t)r * CC) + k0 + ch * 16;
            cp16(sbase + half * STG_A + r * 144 + ch * 16, src);
        }
    };

    issue(sb0,            0); CP_COMMIT();
    issue(sb0 + STG_SZ, 128); CP_COMMIT();

    const int KT = 4;
    for (int kt = 0; kt < KT; kt++) {
        CP_WAIT1();
        __syncthreads();
        int nk = kt + 2;
        if (nk < KT) issue(sb0 + (nk % NSTAGE) * STG_SZ, nk * 128);
        CP_COMMIT();
        uint32_t s = sb0 + (kt % NSTAGE) * STG_SZ;
        compute_stage(s, s + STG_A, wm, wn, lane, acc);
    }

    // ---- epilogue: transpose acc through smem, then fully-coalesced rows ----
    __syncthreads();                     // pipeline smem fully consumed
    float* Sbuf = (float*)dsm;           // [128][132] fp32 = 67.6 KB
#pragma unroll
    for (int mt = 0; mt < 2; mt++) {
        int r0 = wm * 32 + mt * 16 + (lane >> 2);
#pragma unroll
        for (int half = 0; half < 2; half++) {
            int r = r0 + half * 8;
#pragma unroll
            for (int nt = 0; nt < 8; nt++) {
                int col = wn * 64 + nt * 8 + 2 * (lane & 3);
                *(float2*)&Sbuf[r * 132 + col] =
                    make_float2(acc[mt][nt][half * 2], acc[mt][nt][half * 2 + 1]);
            }
        }
    }
    __syncthreads();

    const float gamma = __ldg(gptr);
    const float* csP = g_colsum + b * NN + nb;
    const float* srP = g_srn    + b * NN + nb;
    float4 cs = *(const float4*)(csP + lane * 4);
    float4 sr = *(const float4*)(srP + lane * 4);
    for (int rr = 0; rr < 16; rr++) {
        int row = warp + rr * 8;
        int c = cb + row;
        float tg = gamma / ((float)NN + g_tacc[b * CC + c]);
        float4 S = *(const float4*)&Sbuf[row * 132 + lane * 4];
        size_t go = ((size_t)b * CC + c) * NN + nb + lane * 4;
        float4 xv = *(const float4*)(x + go);
        float4 o;
        o.x = fmaf(tg, fmaf(sr.x, S.x, cs.x), xv.x);
        o.y = fmaf(tg, fmaf(sr.y, S.y, cs.y), xv.y);
        o.z = fmaf(tg, fmaf(sr.z, S.z, cs.z), xv.z);
        o.w = fmaf(tg, fmaf(sr.w, S.w, cs.w), xv.w);
        *(float4*)(out + go) = o;
    }
}

// ===========================================================================
extern "C" void kernel_launch(void* const* d_in, const int* in_sizes, int n_in,
                              void* d_out, int out_size) {
    const float* x     = (const float*)d_in[0];
    const float* gamma = (const float*)d_in[1];
    float* out = (float*)d_out;

    cudaFuncSetAttribute(prep_kernel, cudaFuncAttributeMaxDynamicSharedMemorySize, PREP_SMEM);
    cudaFuncSetAttribute(gemm1_mma,  cudaFuncAttributeMaxDynamicSharedMemorySize, SM_DYN);
    cudaFuncSetAttribute(gemm2_mma,  cudaFuncAttributeMaxDynamicSharedMemorySize, SM_DYN);

    void* taccPtr = nullptr;
    cudaGetSymbolAddress(&taccPtr, g_tacc);
    cudaMemsetAsync(taccPtr, 0, BB * CC * sizeof(float));

    prep_kernel<<<dim3(NN / 64, BB), 512, PREP_SMEM>>>(x);
    gemm1_mma<<<dim3(10, 4, BB), 256, SM_DYN>>>();
    reduce_mirror<<<dim3(4, 10, BB), 256>>>();
    gemm2_mma<<<dim3(NN / 128, CC / 128, BB), 256, SM_DYN>>>(x, gamma, out);
}